// round 14
// baseline (speedup 1.0000x reference)
#include <cuda_runtime.h>

#define THETA 0.5f
#define EPS   1e-5f

// finest-level (p=2) per-patch stats: (sum, sumsq). 512 planes x 16 patches.
__device__ float2 g_stats[512 * 16];

__device__ __forceinline__ float fast_tanh(float x) {
    float y;
    asm("tanh.approx.f32 %0, %1;" : "=f"(y) : "f"(x));
    return y;
}

// ---------- Kernel 1: per-patch stats (read-only streaming) ----------
// One CTA per 64x64 patch. 256 threads, each 4x float4 = 16 elements.
// Plain (caching) loads on purpose: they leave x resident in L2 for kernel 2.
__global__ __launch_bounds__(256) void pmfm_stats(const float* __restrict__ x) {
    const int bc = blockIdx.y;           // plane (b*C + c), forward order
    const int pi = blockIdx.x;           // 0..15 finest patch
    const float* base = x + (size_t)bc * 65536
                          + (size_t)(pi >> 2) * (64 * 256)
                          + (pi & 3) * 64;
    const int t    = threadIdx.x;
    const int col  = (t & 15) << 2;      // float col within 64-wide patch
    const int row0 = t >> 4;             // 0..15

    float4 v[4];
#pragma unroll
    for (int r = 0; r < 4; ++r)
        v[r] = *reinterpret_cast<const float4*>(base + (row0 + (r << 4)) * 256 + col);

    float s = 0.f, ss = 0.f;
#pragma unroll
    for (int r = 0; r < 4; ++r) {
        s  += (v[r].x + v[r].y) + (v[r].z + v[r].w);
        ss += v[r].x * v[r].x + v[r].y * v[r].y + v[r].z * v[r].z + v[r].w * v[r].w;
    }
#pragma unroll
    for (int o = 16; o > 0; o >>= 1) {
        s  += __shfl_xor_sync(0xffffffffu, s,  o);
        ss += __shfl_xor_sync(0xffffffffu, ss, o);
    }
    __shared__ float2 red[8];
    if ((t & 31) == 0) red[t >> 5] = make_float2(s, ss);
    __syncthreads();
    if (t == 0) {
        float S = 0.f, SS = 0.f;
#pragma unroll
        for (int i = 0; i < 8; ++i) { S += red[i].x; SS += red[i].y; }
        g_stats[bc * 16 + pi] = make_float2(S, SS);
    }
}

// ---------- Kernel 2: gate + blend (streaming, REVERSE plane order) ----------
// One CTA per 64x64 patch, planes visited newest-first (511 - blockIdx.y) so
// reads hit the x data kernel 1 left in L2. __ldcs reads (evict-first: no
// pollution), __stcs writes (streaming: don't evict x).
__global__ __launch_bounds__(256) void pmfm_apply(const float* __restrict__ x,
                                                  const float* __restrict__ lw,
                                                  float* __restrict__ out) {
    const int bc = (int)(gridDim.y - 1 - blockIdx.y);   // reverse order
    const int pi = blockIdx.x;

    __shared__ float2 st[16];
    if (threadIdx.x < 16) st[threadIdx.x] = g_stats[bc * 16 + threadIdx.x];
    __syncthreads();

    const int pr = pi >> 2, pc = pi & 3;

    // level 2 (finest): this patch's moments
    const float2 f2 = st[pi];
    // level 1: 2x2 quadrant of finest patches
    float s1 = 0.f, q1 = 0.f;
    {
        const int qr = pr & ~1, qc = pc & ~1;
#pragma unroll
        for (int dr = 0; dr < 2; ++dr)
#pragma unroll
            for (int dc = 0; dc < 2; ++dc) {
                const float2 v = st[(qr + dr) * 4 + (qc + dc)];
                s1 += v.x; q1 += v.y;
            }
    }
    // level 0: whole plane
    float s0 = 0.f, q0 = 0.f;
#pragma unroll
    for (int i = 0; i < 16; ++i) { s0 += st[i].x; q0 += st[i].y; }

    const float iN2 = 1.f / 4096.f, iN1 = 1.f / 16384.f, iN0 = 1.f / 65536.f;
    const float mu2 = f2.x * iN2; const float v2 = fmaxf(f2.y * iN2 - mu2 * mu2, 0.f);
    const float mu1 = s1  * iN1; const float v1 = fmaxf(q1  * iN1 - mu1 * mu1, 0.f);
    const float mu0 = s0  * iN0; const float v0 = fmaxf(q0  * iN0 - mu0 * mu0, 0.f);

    // sigmoid(z) = 0.5 + 0.5*tanh(z/2); arg = x*a + b, a = 0.5*rsig, b = -mu*a
    const float a2 = 0.5f * rsqrtf(v2 + EPS), b2 = -mu2 * a2;
    const float a1 = 0.5f * rsqrtf(v1 + EPS), b1 = -mu1 * a1;
    const float a0 = 0.5f * rsqrtf(v0 + EPS), b0 = -mu0 * a0;

    // softmax(level_weights); lw[0] pairs with p=2 (finest), lw[2] with p=0
    const float w0 = __ldg(lw + 0), w1 = __ldg(lw + 1), w2 = __ldg(lw + 2);
    const float m  = fmaxf(w0, fmaxf(w1, w2));
    const float e0 = __expf(w0 - m), e1 = __expf(w1 - m), e2 = __expf(w2 - m);
    const float c  = (1.f - THETA) * 0.5f / (e0 + e1 + e2);
    const float cf = c * e0, cm = c * e1, cg = c * e2;
    const float basew = THETA + (1.f - THETA) * 0.5f;

    const size_t off = (size_t)bc * 65536 + (size_t)pr * (64 * 256) + pc * 64;
    const float* xin = x + off;
    float* o = out + off;
    const int t    = threadIdx.x;
    const int col  = (t & 15) << 2;
    const int row0 = t >> 4;

    // batched loads first (MLP=4), then compute+store
    float4 v[4];
#pragma unroll
    for (int r = 0; r < 4; ++r)
        v[r] = __ldcs(reinterpret_cast<const float4*>(xin + (row0 + (r << 4)) * 256 + col));

#pragma unroll
    for (int r = 0; r < 4; ++r) {
        const int idx = (row0 + (r << 4)) * 256 + col;
        float4 res;
#define PMFM_DO(comp)                                                     \
        {                                                                 \
            const float xx = v[r].comp;                                   \
            const float tf = fast_tanh(fmaf(xx, a2, b2));                 \
            const float tm = fast_tanh(fmaf(xx, a1, b1));                 \
            const float tg = fast_tanh(fmaf(xx, a0, b0));                 \
            const float f  = fmaf(cf, tf, fmaf(cm, tm, fmaf(cg, tg, basew))); \
            res.comp = xx * f;                                            \
        }
        PMFM_DO(x) PMFM_DO(y) PMFM_DO(z) PMFM_DO(w)
#undef PMFM_DO
        __stcs(reinterpret_cast<float4*>(o + idx), res);
    }
}

extern "C" void kernel_launch(void* const* d_in, const int* in_sizes, int n_in,
                              void* d_out, int out_size) {
    const float* x;
    const float* lw;
    long nx;
    if (in_sizes[0] >= in_sizes[1]) {
        x = (const float*)d_in[0]; lw = (const float*)d_in[1]; nx = in_sizes[0];
    } else {
        x = (const float*)d_in[1]; lw = (const float*)d_in[0]; nx = in_sizes[1];
    }
    const int nplanes = (int)(nx / 65536);   // B*C = 512 planes of 256x256
    dim3 grid(16, nplanes);
    pmfm_stats<<<grid, 256>>>(x);
    pmfm_apply<<<grid, 256>>>(x, lw, (float*)d_out);
}